// round 2
// baseline (speedup 1.0000x reference)
#include <cuda_runtime.h>
#include <cstdint>

#define B_    64
#define T_    512
#define H_    1024
#define D_    512
#define GB_   4     // batch groups
#define CPG_  32    // CTAs per group
#define BPG_  16    // batches per group
#define CHPC_ 32    // channels per CTA
#define NCTA_ (GB_*CPG_)
#define NTHR_ 256

// scratch (static __device__ arrays: allocation-free)
__device__ float  g_u[(size_t)T_ * B_ * H_];        // u drive, [t][b][h]
__device__ float  g_state[2][B_][H_];               // ping-pong recurrent state
__device__ float2 g_red[2][B_][CPG_];               // LN partial sums (sum, sumsq)
__device__ int    g_bar[T_][GB_];                   // per-step per-group barrier counters

__global__ void init_kernel() {
    int i = blockIdx.x * blockDim.x + threadIdx.x;
    if (i < 2 * B_ * H_) ((float*)g_state)[i] = 0.0f;
    if (i < T_ * GB_)    ((int*)g_bar)[i] = 0;
}

// packed 2-wide fp32 FMA (sm_103a FFMA2 — only reachable via PTX)
__device__ __forceinline__ void fma2(unsigned long long& acc,
                                     unsigned long long a,
                                     unsigned long long b) {
    asm("fma.rn.f32x2 %0, %1, %2, %0;" : "+l"(acc) : "l"(a), "l"(b));
}
__device__ __forceinline__ float f2_lo(unsigned long long v) {
    return __uint_as_float((unsigned)(v & 0xffffffffull));
}
__device__ __forceinline__ float f2_hi(unsigned long long v) {
    return __uint_as_float((unsigned)(v >> 32));
}

// ---------------------------------------------------------------------------
// u[t][b][h] = sum_d x[b][t][d] * W_in[h][d] + b_in[h]
// classic 128x128x8 fp32 tiled GEMM, M = B*T (m = b*512 + t), N = H, K = D
// ---------------------------------------------------------------------------
__global__ __launch_bounds__(256) void u_gemm(const float* __restrict__ X,
                                              const float* __restrict__ Win,
                                              const float* __restrict__ bin) {
    __shared__ float As[8][128];
    __shared__ float Bs[8][128];
    int n0 = blockIdx.x * 128;
    int m0 = blockIdx.y * 128;
    int tid = threadIdx.x;
    int tm = tid >> 4, tn = tid & 15;

    float acc[8][8];
#pragma unroll
    for (int i = 0; i < 8; i++)
#pragma unroll
        for (int j = 0; j < 8; j++) acc[i][j] = 0.0f;

    int arow = tid >> 1;
    int ac4  = (tid & 1) * 4;
    const float* Aptr = X   + (size_t)(m0 + arow) * D_ + ac4;
    const float* Bptr = Win + (size_t)(n0 + arow) * D_ + ac4;

    for (int k0 = 0; k0 < D_; k0 += 8) {
        float4 av = *(const float4*)(Aptr + k0);
        float4 bv = *(const float4*)(Bptr + k0);
        As[ac4 + 0][arow] = av.x; As[ac4 + 1][arow] = av.y;
        As[ac4 + 2][arow] = av.z; As[ac4 + 3][arow] = av.w;
        Bs[ac4 + 0][arow] = bv.x; Bs[ac4 + 1][arow] = bv.y;
        Bs[ac4 + 2][arow] = bv.z; Bs[ac4 + 3][arow] = bv.w;
        __syncthreads();
#pragma unroll
        for (int kk = 0; kk < 8; kk++) {
            float rm[8], rn[8];
            *(float4*)(rm)     = *(const float4*)&As[kk][tm * 8];
            *(float4*)(rm + 4) = *(const float4*)&As[kk][tm * 8 + 4];
            *(float4*)(rn)     = *(const float4*)&Bs[kk][tn * 8];
            *(float4*)(rn + 4) = *(const float4*)&Bs[kk][tn * 8 + 4];
#pragma unroll
            for (int i = 0; i < 8; i++)
#pragma unroll
                for (int j = 0; j < 8; j++)
                    acc[i][j] = fmaf(rm[i], rn[j], acc[i][j]);
        }
        __syncthreads();
    }

    float bias[8];
    *(float4*)(bias)     = *(const float4*)&bin[n0 + tn * 8];
    *(float4*)(bias + 4) = *(const float4*)&bin[n0 + tn * 8 + 4];

#pragma unroll
    for (int i = 0; i < 8; i++) {
        int m  = m0 + tm * 8 + i;
        int tt = m & (T_ - 1);
        int bb = m >> 9;
        float* dst = g_u + ((size_t)tt * B_ + bb) * H_ + n0 + tn * 8;
        float4 v0, v1;
        v0.x = acc[i][0] + bias[0]; v0.y = acc[i][1] + bias[1];
        v0.z = acc[i][2] + bias[2]; v0.w = acc[i][3] + bias[3];
        v1.x = acc[i][4] + bias[4]; v1.y = acc[i][5] + bias[5];
        v1.z = acc[i][6] + bias[6]; v1.w = acc[i][7] + bias[7];
        *(float4*)(dst)     = v0;
        *(float4*)(dst + 4) = v1;
    }
}

// ---------------------------------------------------------------------------
// Persistent recurrence kernel: 128 CTAs = 4 batch-groups x 32 CTAs.
// CTA (g, jc): batches [16g,16g+16), channels [32jc, 32jc+32).
// W slice + group state in SMEM; per-step per-group global barrier.
// GEMM inner loop uses packed fma.rn.f32x2 (K-pairs in .b64 regs).
// ---------------------------------------------------------------------------
__global__ __launch_bounds__(256, 1) void rec_kernel(
    const float* __restrict__ Wst, const float* __restrict__ bst,
    const float* __restrict__ decay, const float* __restrict__ gamma,
    const float* __restrict__ beta, float* __restrict__ out) {
    extern __shared__ float smem[];
    float* Wsm    = smem;                      // [32][1024]
    float* Ssm    = smem + CHPC_ * H_;         // [16][1024]
    float* red_sm = Ssm + BPG_ * H_;           // [16][8][2]

    int g   = blockIdx.x / CPG_;
    int jc  = blockIdx.x % CPG_;
    int ch0 = jc * CHPC_;
    int b0  = g * BPG_;
    int tid = threadIdx.x;
    int w = tid >> 5, l = tid & 31;

    // load W_state slice (rows ch0..ch0+31, contiguous) into SMEM
    {
        const float4* src = (const float4*)(Wst + (size_t)ch0 * H_);
        float4* dst = (float4*)Wsm;
        for (int v = tid; v < CHPC_ * H_ / 4; v += NTHR_) dst[v] = __ldg(src + v);
    }

    // lane ownership: after reduce-scatter, lane l owns outputs o=2l,2l+1
    // o = b*4 + c  ->  b = l>>1, c = 2*(l&1) + {0,1}; channel = ch0 + 4w + c
    int myb  = l >> 1;
    int gb   = b0 + myb;
    int c0   = (l & 1) * 2;
    int mych = ch0 + w * 4 + c0;

    float dd0 = 1.0f / (1.0f + expf(-decay[mych]));
    float dd1 = 1.0f / (1.0f + expf(-decay[mych + 1]));
    float bs0 = bst[mych],   bs1 = bst[mych + 1];
    float ga0 = gamma[mych], ga1 = gamma[mych + 1];
    float be0 = beta[mych],  be1 = beta[mych + 1];
    const unsigned FULL = 0xffffffffu;

    __syncthreads();

    for (int t = 0; t < T_; ++t) {
        int p = t & 1, p2 = p ^ 1;
        // prefetch input drive for my 2 channels
        float2 uv = *(const float2*)(g_u + ((size_t)t * B_ + gb) * H_ + mych);

        // pull group state (written by all group CTAs last step) into SMEM; .cg avoids stale L1
        {
            const float4* src = (const float4*)(&g_state[p][b0][0]);
            float4* dst = (float4*)Ssm;
#pragma unroll
            for (int v = tid; v < BPG_ * H_ / 4; v += NTHR_) dst[v] = __ldcg(src + v);
        }
        __syncthreads();

        // GEMM: warp w computes channels 4w..4w+3 for 16 batches, K split over lanes.
        // Packed f32x2: each b64 accumulator holds (even-K partial, odd-K partial).
        unsigned long long acc[64];
#pragma unroll
        for (int o = 0; o < 64; o++) acc[o] = 0ull;
#pragma unroll 1
        for (int i = 0; i < 8; i++) {
            int kb = i * 128 + l * 4;
            ulonglong2 wv[4];
#pragma unroll
            for (int c = 0; c < 4; c++)
                wv[c] = *(const ulonglong2*)&Wsm[(w * 4 + c) * H_ + kb];
#pragma unroll
            for (int b = 0; b < 16; b++) {
                ulonglong2 sv = *(const ulonglong2*)&Ssm[b * H_ + kb];
#pragma unroll
                for (int c = 0; c < 4; c++) {
                    fma2(acc[b * 4 + c], sv.x, wv[c].x);
                    fma2(acc[b * 4 + c], sv.y, wv[c].y);
                }
            }
        }

        // collapse packed halves -> 64 scalars
        float accf[64];
#pragma unroll
        for (int o = 0; o < 64; o++) accf[o] = f2_lo(acc[o]) + f2_hi(acc[o]);

        // reduce-scatter across lanes: lane l ends owning accf[0],accf[1] = outputs 2l,2l+1
#pragma unroll
        for (int delta = 16; delta >= 1; delta >>= 1) {
            const int num = 2 * delta;
            bool up = (l & delta) != 0;
#pragma unroll
            for (int q = 0; q < num; q++) {
                float send = up ? accf[q] : accf[q + num];
                float recv = __shfl_xor_sync(FULL, send, delta);
                accf[q] = (up ? accf[q + num] : accf[q]) + recv;
            }
        }

        float sold0 = Ssm[myb * H_ + mych];
        float sold1 = Ssm[myb * H_ + mych + 1];
        float dr0 = tanhf(uv.x + accf[0] + bs0);
        float dr1 = tanhf(uv.y + accf[1] + bs1);
        float sn0 = dd0 * sold0 + (1.0f - dd0) * dr0;
        float sn1 = dd1 * sold1 + (1.0f - dd1) * dr1;
        *(float2*)&g_state[p2][gb][mych] = make_float2(sn0, sn1);

        // LN partials: per-(batch,warp) 4-channel sums -> CTA 32-channel sums -> global slot
        float ps = sn0 + sn1, pq = sn0 * sn0 + sn1 * sn1;
        ps += __shfl_xor_sync(FULL, ps, 1);
        pq += __shfl_xor_sync(FULL, pq, 1);
        if ((l & 1) == 0) {
            red_sm[(myb * 8 + w) * 2 + 0] = ps;
            red_sm[(myb * 8 + w) * 2 + 1] = pq;
        }
        __syncthreads();
        if (tid < BPG_) {
            float S = 0.0f, Q = 0.0f;
#pragma unroll
            for (int ww = 0; ww < 8; ww++) {
                S += red_sm[(tid * 8 + ww) * 2 + 0];
                Q += red_sm[(tid * 8 + ww) * 2 + 1];
            }
            g_red[p][b0 + tid][jc] = make_float2(S, Q);
        }
        __threadfence();
        __syncthreads();
        // per-group barrier: fresh counter per step (zeroed by init kernel)
        if (tid == 0) {
            atomicAdd(&g_bar[t][g], 1);
            volatile int* flag = &g_bar[t][g];
            while (*flag < CPG_) { }
        }
        __syncthreads();

        // LayerNorm: deterministic fixed-order reduce over the 32 CTA partials
        float S = 0.0f, Q = 0.0f;
#pragma unroll
        for (int jj = 0; jj < CPG_; jj++) {
            float2 v = __ldcg(&g_red[p][gb][jj]);
            S += v.x; Q += v.y;
        }
        float mean = S * (1.0f / H_);
        float var  = Q * (1.0f / H_) - mean * mean;
        float rstd = rsqrtf(var + 1e-5f);
        float2 yv;
        yv.x = (sn0 - mean) * rstd * ga0 + be0;
        yv.y = (sn1 - mean) * rstd * ga1 + be1;
        *(float2*)(out + ((size_t)gb * T_ + t) * H_ + mych) = yv;
    }
}

extern "C" void kernel_launch(void* const* d_in, const int* in_sizes, int n_in,
                              void* d_out, int out_size) {
    const float* x     = (const float*)d_in[0];
    const float* Win   = (const float*)d_in[1];
    const float* bin   = (const float*)d_in[2];
    const float* Wst   = (const float*)d_in[3];
    const float* bst   = (const float*)d_in[4];
    const float* decay = (const float*)d_in[5];
    const float* gamma = (const float*)d_in[6];
    const float* beta  = (const float*)d_in[7];
    float* out = (float*)d_out;

    const int smem_bytes = (CHPC_ * H_ + BPG_ * H_ + BPG_ * 8 * 2) * sizeof(float); // 197632
    cudaFuncSetAttribute(rec_kernel, cudaFuncAttributeMaxDynamicSharedMemorySize, smem_bytes);

    init_kernel<<<512, 256>>>();
    dim3 gg(H_ / 128, (B_ * T_) / 128);
    u_gemm<<<gg, 256>>>(x, Win, bin);
    rec_kernel<<<NCTA_, 256, smem_bytes>>>(Wst, bst, decay, gamma, beta, out);
}

// round 3
// speedup vs baseline: 1.5080x; 1.5080x over previous
#include <cuda_runtime.h>
#include <cstdint>

#define B_    64
#define T_    512
#define H_    1024
#define D_    512
#define GB_   4     // batch groups
#define CPG_  32    // CTAs per group (= chunks per group)
#define BPG_  16    // batches per group
#define CHPC_ 32    // channels per CTA (= K-chunk width)
#define NCTA_ (GB_*CPG_)
#define NTHR_ 256
#define SLOTS_ 4

// scratch (static __device__ arrays: zero at module load, allocation-free)
__device__ float  g_u[(size_t)T_ * B_ * H_];           // u drive [t][b][h]
__device__ float  g_stt[SLOTS_][B_][H_];               // state slots (depth 4)
__device__ float2 g_redp[SLOTS_][B_][CPG_];            // LN partials (depth 4)
__device__ int    g_flag[T_ + 1][GB_][CPG_];           // monotonic chunk-ready counters

// packed 2-wide fp32 FMA (sm_103a FFMA2, PTX-only)
__device__ __forceinline__ void fma2(unsigned long long& acc,
                                     unsigned long long a,
                                     unsigned long long b) {
    asm("fma.rn.f32x2 %0, %1, %2, %0;" : "+l"(acc) : "l"(a), "l"(b));
}
__device__ __forceinline__ float f2_lo(unsigned long long v) {
    return __uint_as_float((unsigned)(v & 0xffffffffull));
}
__device__ __forceinline__ float f2_hi(unsigned long long v) {
    return __uint_as_float((unsigned)(v >> 32));
}

// ---------------------------------------------------------------------------
// u[t][b][h] = sum_d x[b][t][d] * W_in[h][d] + b_in[h]
// ---------------------------------------------------------------------------
__global__ __launch_bounds__(256) void u_gemm(const float* __restrict__ X,
                                              const float* __restrict__ Win,
                                              const float* __restrict__ bin) {
    __shared__ float As[8][128];
    __shared__ float Bs[8][128];
    int n0 = blockIdx.x * 128;
    int m0 = blockIdx.y * 128;
    int tid = threadIdx.x;
    int tm = tid >> 4, tn = tid & 15;

    float acc[8][8];
#pragma unroll
    for (int i = 0; i < 8; i++)
#pragma unroll
        for (int j = 0; j < 8; j++) acc[i][j] = 0.0f;

    int arow = tid >> 1;
    int ac4  = (tid & 1) * 4;
    const float* Aptr = X   + (size_t)(m0 + arow) * D_ + ac4;
    const float* Bptr = Win + (size_t)(n0 + arow) * D_ + ac4;

    for (int k0 = 0; k0 < D_; k0 += 8) {
        float4 av = *(const float4*)(Aptr + k0);
        float4 bv = *(const float4*)(Bptr + k0);
        As[ac4 + 0][arow] = av.x; As[ac4 + 1][arow] = av.y;
        As[ac4 + 2][arow] = av.z; As[ac4 + 3][arow] = av.w;
        Bs[ac4 + 0][arow] = bv.x; Bs[ac4 + 1][arow] = bv.y;
        Bs[ac4 + 2][arow] = bv.z; Bs[ac4 + 3][arow] = bv.w;
        __syncthreads();
#pragma unroll
        for (int kk = 0; kk < 8; kk++) {
            float rm[8], rn[8];
            *(float4*)(rm)     = *(const float4*)&As[kk][tm * 8];
            *(float4*)(rm + 4) = *(const float4*)&As[kk][tm * 8 + 4];
            *(float4*)(rn)     = *(const float4*)&Bs[kk][tn * 8];
            *(float4*)(rn + 4) = *(const float4*)&Bs[kk][tn * 8 + 4];
#pragma unroll
            for (int i = 0; i < 8; i++)
#pragma unroll
                for (int j = 0; j < 8; j++)
                    acc[i][j] = fmaf(rm[i], rn[j], acc[i][j]);
        }
        __syncthreads();
    }

    float bias[8];
    *(float4*)(bias)     = *(const float4*)&bin[n0 + tn * 8];
    *(float4*)(bias + 4) = *(const float4*)&bin[n0 + tn * 8 + 4];

#pragma unroll
    for (int i = 0; i < 8; i++) {
        int m  = m0 + tm * 8 + i;
        int tt = m & (T_ - 1);
        int bb = m >> 9;
        float* dst = g_u + ((size_t)tt * B_ + bb) * H_ + n0 + tn * 8;
        float4 v0, v1;
        v0.x = acc[i][0] + bias[0]; v0.y = acc[i][1] + bias[1];
        v0.z = acc[i][2] + bias[2]; v0.w = acc[i][3] + bias[3];
        v1.x = acc[i][4] + bias[4]; v1.y = acc[i][5] + bias[5];
        v1.z = acc[i][6] + bias[6]; v1.w = acc[i][7] + bias[7];
        *(float4*)(dst)     = v0;
        *(float4*)(dst + 4) = v1;
    }
}

// ---------------------------------------------------------------------------
// Persistent recurrence kernel with per-chunk flag pipeline (no full barrier).
// CTA (g,jc): batches [16g,16g+16), channels [32jc,32jc+32).
// K processed in 8 groups of 128 (4 chunks each); group loads double-buffered.
// LayerNorm of step t-1 computed during step t.
// ---------------------------------------------------------------------------
__global__ __launch_bounds__(256, 1) void rec_kernel(
    const float* __restrict__ Wst, const float* __restrict__ bst,
    const float* __restrict__ decay, const float* __restrict__ gamma,
    const float* __restrict__ beta, float* __restrict__ out) {
    extern __shared__ float smem[];
    float* Wsm    = smem;                    // [32][1024] = 32768 floats
    float* Ssm    = smem + CHPC_ * H_;       // 2 bufs x [16][128] = 4096 floats
    float* red_sm = Ssm + 2 * BPG_ * 128;    // [16][8][2] = 256 floats
    float* bcast  = red_sm + 256;            // [16][2] mean/rstd + epoch slot

    int g   = blockIdx.x / CPG_;
    int jc  = blockIdx.x % CPG_;
    int ch0 = jc * CHPC_;
    int b0  = g * BPG_;
    int tid = threadIdx.x;
    int w = tid >> 5, l = tid & 31;

    // load W_state slice (rows ch0..ch0+31, contiguous)
    {
        const float4* src = (const float4*)(Wst + (size_t)ch0 * H_);
        float4* dst = (float4*)Wsm;
        for (int v = tid; v < CHPC_ * H_ / 4; v += NTHR_) dst[v] = __ldg(src + v);
    }

    int myb  = l >> 1;
    int gb   = b0 + myb;
    int mych = ch0 + w * 4 + (l & 1) * 2;

    float dd0 = 1.0f / (1.0f + expf(-decay[mych]));
    float dd1 = 1.0f / (1.0f + expf(-decay[mych + 1]));
    float bs0 = bst[mych],   bs1 = bst[mych + 1];
    float ga0 = gamma[mych], ga1 = gamma[mych + 1];
    float be0 = beta[mych],  be1 = beta[mych + 1];
    const unsigned FULL = 0xffffffffu;

    // loader indices: thread covers float4 elements v=tid and v=tid+256 of a group
    int ldb  = tid >> 5;        // batch rows ldb and ldb+8
    int ldc4 = tid & 31;        // float4 column within 128-float group

    __syncthreads();

    float snp0, snp1;  // my state, kept in registers across steps
    int target;        // flag epoch target for this replay

    // ---------------- t = 0 : state is zero ----------------
    {
        float2 uv = *(const float2*)(g_u + (size_t)gb * H_ + mych);
        float dr0 = tanhf(uv.x + bs0);
        float dr1 = tanhf(uv.y + bs1);
        snp0 = (1.0f - dd0) * dr0;
        snp1 = (1.0f - dd1) * dr1;
        __stcg((float2*)&g_stt[1][gb][mych], make_float2(snp0, snp1));

        float ps = snp0 + snp1, pq = snp0 * snp0 + snp1 * snp1;
        ps += __shfl_xor_sync(FULL, ps, 1);
        pq += __shfl_xor_sync(FULL, pq, 1);
        if ((l & 1) == 0) {
            red_sm[(myb * 8 + w) * 2 + 0] = ps;
            red_sm[(myb * 8 + w) * 2 + 1] = pq;
        }
        __syncthreads();
        if (tid < BPG_) {
            float S = 0.0f, Q = 0.0f;
#pragma unroll
            for (int ww = 0; ww < 8; ww++) {
                S += red_sm[(tid * 8 + ww) * 2 + 0];
                Q += red_sm[(tid * 8 + ww) * 2 + 1];
            }
            __stcg(&g_redp[0][b0 + tid][jc], make_float2(S, Q));
        }
        __threadfence();
        __syncthreads();
        if (tid == 0) {
            int old = atomicAdd(&g_flag[1][g][jc], 1);
            bcast[32] = __int_as_float(old + 1);
        }
        __syncthreads();
        target = __float_as_int(bcast[32]);
    }

    // ---------------- main loop t = 1..T-1 ----------------
    for (int t = 1; t < T_; ++t) {
        int slot  = t & 3;
        int wslot = (t + 1) & 3;
        int rslot = (t - 1) & 3;
        float2 uv = *(const float2*)(g_u + ((size_t)t * B_ + gb) * H_ + mych);

        unsigned long long acc[64];
#pragma unroll
        for (int o = 0; o < 64; o++) acc[o] = 0ull;

        const float4* srow = (const float4*)&g_stt[slot][b0][0];  // 256 float4/row

        // prologue: group seq(0)
        {
            int s0 = jc & 7;
            if (tid < 4) {
                volatile int* fp = &g_flag[t][g][4 * s0 + tid];
                while (*fp < target) {}
            }
            __syncthreads();
            float4 r0 = __ldcg(&srow[ldb * 256 + s0 * 32 + ldc4]);
            float4 r1 = __ldcg(&srow[(ldb + 8) * 256 + s0 * 32 + ldc4]);
            float4* d = (float4*)Ssm;
            d[ldb * 32 + ldc4] = r0;
            d[(ldb + 8) * 32 + ldc4] = r1;
            __syncthreads();
        }

#pragma unroll 2
        for (int i = 0; i < 8; ++i) {
            int sg  = (i + jc) & 7;
            int buf = i & 1;
            float4 n0, n1;
            if (i < 7) {
                int sgn = (i + 1 + jc) & 7;
                if (tid < 4) {
                    volatile int* fp = &g_flag[t][g][4 * sgn + tid];
                    while (*fp < target) {}
                }
                __syncthreads();
                n0 = __ldcg(&srow[ldb * 256 + sgn * 32 + ldc4]);
                n1 = __ldcg(&srow[(ldb + 8) * 256 + sgn * 32 + ldc4]);
            }
            // GEMM on group sg from buffer buf (LDG latency hides under this)
            {
                const float* sb = Ssm + buf * (BPG_ * 128);
                ulonglong2 wv[4];
#pragma unroll
                for (int c = 0; c < 4; c++)
                    wv[c] = *(const ulonglong2*)&Wsm[(w * 4 + c) * H_ + sg * 128 + l * 4];
#pragma unroll
                for (int b = 0; b < 16; b++) {
                    ulonglong2 sv = *(const ulonglong2*)&sb[b * 128 + l * 4];
#pragma unroll
                    for (int c = 0; c < 4; c++) {
                        fma2(acc[b * 4 + c], sv.x, wv[c].x);
                        fma2(acc[b * 4 + c], sv.y, wv[c].y);
                    }
                }
            }
            if (i < 7) {
                float4* d = (float4*)(Ssm + (buf ^ 1) * (BPG_ * 128));
                d[ldb * 32 + ldc4] = n0;
                d[(ldb + 8) * 32 + ldc4] = n1;
                __syncthreads();
            }
        }

        // deferred LayerNorm for step t-1 (all flags[t] observed => g_redp[rslot] visible)
        if (tid < BPG_) {
            const float4* rp = (const float4*)&g_redp[rslot][b0 + tid][0];
            float S = 0.0f, Q = 0.0f;
#pragma unroll
            for (int q = 0; q < 16; q++) {
                float4 v = __ldcg(&rp[q]);
                S += v.x + v.z; Q += v.y + v.w;
            }
            float mean = S * (1.0f / H_);
            float var  = Q * (1.0f / H_) - mean * mean;
            bcast[tid * 2 + 0] = mean;
            bcast[tid * 2 + 1] = rsqrtf(var + 1e-5f);
        }
        __syncthreads();
        {
            float mean = bcast[myb * 2 + 0], rstd = bcast[myb * 2 + 1];
            float2 yv;
            yv.x = (snp0 - mean) * rstd * ga0 + be0;
            yv.y = (snp1 - mean) * rstd * ga1 + be1;
            *(float2*)(out + ((size_t)gb * T_ + (t - 1)) * H_ + mych) = yv;
        }

        // reduce-scatter: collapse packed halves, 5-level shuffle
        float accf[64];
#pragma unroll
        for (int o = 0; o < 64; o++) accf[o] = f2_lo(acc[o]) + f2_hi(acc[o]);
#pragma unroll
        for (int delta = 16; delta >= 1; delta >>= 1) {
            const int num = 2 * delta;
            bool up = (l & delta) != 0;
#pragma unroll
            for (int q = 0; q < num; q++) {
                float send = up ? accf[q] : accf[q + num];
                float recv = __shfl_xor_sync(FULL, send, delta);
                accf[q] = (up ? accf[q + num] : accf[q]) + recv;
            }
        }

        float dr0 = tanhf(uv.x + accf[0] + bs0);
        float dr1 = tanhf(uv.y + accf[1] + bs1);
        float sn0 = dd0 * snp0 + (1.0f - dd0) * dr0;
        float sn1 = dd1 * snp1 + (1.0f - dd1) * dr1;
        __stcg((float2*)&g_stt[wslot][gb][mych], make_float2(sn0, sn1));

        float ps = sn0 + sn1, pq = sn0 * sn0 + sn1 * sn1;
        ps += __shfl_xor_sync(FULL, ps, 1);
        pq += __shfl_xor_sync(FULL, pq, 1);
        if ((l & 1) == 0) {
            red_sm[(myb * 8 + w) * 2 + 0] = ps;
            red_sm[(myb * 8 + w) * 2 + 1] = pq;
        }
        __syncthreads();
        if (tid < BPG_) {
            float S = 0.0f, Q = 0.0f;
#pragma unroll
            for (int ww = 0; ww < 8; ww++) {
                S += red_sm[(tid * 8 + ww) * 2 + 0];
                Q += red_sm[(tid * 8 + ww) * 2 + 1];
            }
            __stcg(&g_redp[slot][b0 + tid][jc], make_float2(S, Q));
        }
        __threadfence();
        __syncthreads();
        if (tid == 0) atomicAdd(&g_flag[t + 1][g][jc], 1);

        snp0 = sn0; snp1 = sn1;
    }

    // ---------------- final LayerNorm for t = T-1 ----------------
    if (tid < 32) {
        volatile int* fp = &g_flag[T_][g][tid];
        while (*fp < target) {}
    }
    __syncthreads();
    {
        int rslot = (T_ - 1) & 3;
        if (tid < BPG_) {
            const float4* rp = (const float4*)&g_redp[rslot][b0 + tid][0];
            float S = 0.0f, Q = 0.0f;
#pragma unroll
            for (int q = 0; q < 16; q++) {
                float4 v = __ldcg(&rp[q]);
                S += v.x + v.z; Q += v.y + v.w;
            }
            float mean = S * (1.0f / H_);
            float var  = Q * (1.0f / H_) - mean * mean;
            bcast[tid * 2 + 0] = mean;
            bcast[tid * 2 + 1] = rsqrtf(var + 1e-5f);
        }
        __syncthreads();
        float mean = bcast[myb * 2 + 0], rstd = bcast[myb * 2 + 1];
        float2 yv;
        yv.x = (snp0 - mean) * rstd * ga0 + be0;
        yv.y = (snp1 - mean) * rstd * ga1 + be1;
        *(float2*)(out + ((size_t)gb * T_ + (T_ - 1)) * H_ + mych) = yv;
    }
}

extern "C" void kernel_launch(void* const* d_in, const int* in_sizes, int n_in,
                              void* d_out, int out_size) {
    const float* x     = (const float*)d_in[0];
    const float* Win   = (const float*)d_in[1];
    const float* bin   = (const float*)d_in[2];
    const float* Wst   = (const float*)d_in[3];
    const float* bst   = (const float*)d_in[4];
    const float* decay = (const float*)d_in[5];
    const float* gamma = (const float*)d_in[6];
    const float* beta  = (const float*)d_in[7];
    float* out = (float*)d_out;

    const int smem_bytes = (CHPC_ * H_ + 2 * BPG_ * 128 + 256 + 40) * sizeof(float);
    cudaFuncSetAttribute(rec_kernel, cudaFuncAttributeMaxDynamicSharedMemorySize, smem_bytes);

    dim3 gg(H_ / 128, (B_ * T_) / 128);
    u_gemm<<<gg, 256>>>(x, Win, bin);
    rec_kernel<<<NCTA_, 256, smem_bytes>>>(Wst, bst, decay, gamma, beta, out);
}